// round 14
// baseline (speedup 1.0000x reference)
#include <cuda_runtime.h>
#include <cuda_fp16.h>
#include <cstdint>

#define BATCH 8
#define SEQ   2048
#define EMB   1024
#define HD    128

// K pre-scale: sqrt(HD^-0.5 * log2(e)) — K is also Q, so MMA yields S*scale*log2e.
#define KSCALE 0.35709512f

#define N_ATTN 640            // 80 items x 8 batches

// ---------------- scratch (allocation-free rule) ----------------
__device__ __half g_Kh [BATCH * SEQ * HD];       // K(scaled), fp16, h interleave-32
__device__ __half g_Vth[BATCH * HD * SEQ];       // V^T [b][h][t], fp16, t interleave-32
__device__ __half g_Wh [2 * HD * EMB];           // [Wk^T;Wv^T] [256][1024], c interleave-32
__device__ float  g_Opart[4 * BATCH * SEQ * HD]; // per-chunk unnormalized O
__device__ float  g_lpart[4 * BATCH * SEQ];      // per-chunk row sums
__device__ int    g_cnt[BATCH * 32];             // per (b, qt64) finished-chunk counters
__device__ int    g_qhead;                       // attn work queue head

// Attn items: (qt, ch), q-tile = 64 rows, chunk = kv64 tiles [8ch, min(8ch+8, qt+1)).
// Big-first ordering. Global item id: idx = it>>3, b = it&7.
__constant__ unsigned char ITEM_QT[80] = {
    31,31,31,31,
    30,30,30, 29,29,29, 28,28,28, 27,27,27, 26,26,26, 25,25,25, 24,24,24, 23,23,23,
    22,22, 21,21, 20,20, 19,19, 18,18, 17,17, 16,16, 15,15,
    14, 13, 12, 11, 10, 9, 8, 7,
    30,22,14,6, 29,21,13,5, 28,20,12,4, 27,19,11,3, 26,18,10,2, 25,17,9,1, 24,16,8,0 };
__constant__ unsigned char ITEM_CH[80] = {
    0,1,2,3,
    0,1,2, 0,1,2, 0,1,2, 0,1,2, 0,1,2, 0,1,2, 0,1,2, 0,1,2,
    0,1, 0,1, 0,1, 0,1, 0,1, 0,1, 0,1, 0,1,
    0, 0, 0, 0, 0, 0, 0, 0,
    3,2,1,0, 3,2,1,0, 3,2,1,0, 3,2,1,0, 3,2,1,0, 3,2,1,0, 3,2,1,0 };

// ---------------- helpers ----------------
__device__ __forceinline__ void cp16(void* s, const void* g) {
    asm volatile("cp.async.cg.shared.global [%0], [%1], 16;"
                 :: "r"((uint32_t)__cvta_generic_to_shared(s)), "l"(g));
}
#define CP_COMMIT() asm volatile("cp.async.commit_group;" ::: "memory")
template <int N>
__device__ __forceinline__ void cp_wait() {
    asm volatile("cp.async.wait_group %0;" :: "n"(N) : "memory");
}
__device__ __forceinline__ uint32_t packh2(float lo, float hi) {
    uint32_t d;
    asm("cvt.rn.f16x2.f32 %0, %1, %2;" : "=r"(d) : "f"(hi), "f"(lo));
    return d;
}
__device__ __forceinline__ uint32_t ex2h2(uint32_t a) {
    uint32_t d;
    asm("ex2.approx.f16x2 %0, %1;" : "=r"(d) : "r"(a));
    return d;
}
__device__ __forceinline__ void mma16(float* d, const uint32_t* a, uint32_t b0, uint32_t b1) {
    asm volatile("mma.sync.aligned.m16n8k16.row.col.f32.f16.f16.f32 "
        "{%0,%1,%2,%3}, {%4,%5,%6,%7}, {%8,%9}, {%0,%1,%2,%3};"
        : "+f"(d[0]), "+f"(d[1]), "+f"(d[2]), "+f"(d[3])
        : "r"(a[0]), "r"(a[1]), "r"(a[2]), "r"(a[3]), "r"(b0), "r"(b1));
}
// interleave-32: 16B granule g holds logical cols {2g,2g+1,2g+8,2g+9,2g+16,2g+17,2g+24,2g+25}
__device__ __forceinline__ int pos32(int c) {
    return 8 * ((c & 7) >> 1) + (c & 1) + 2 * ((c >> 3) & 1) + 4 * ((c >> 4) & 1);
}

// ---------------------------------------------------------------------------
// Kernel R: reset counters + queue head (separate launch; keeps 4 launches so
// ncu's capture index lands on attn_kernel).
// ---------------------------------------------------------------------------
__global__ void reset_kernel() {
    if (threadIdx.x < BATCH * 32) g_cnt[threadIdx.x] = 0;
    if (threadIdx.x == 0) g_qhead = 0;
}

// ---------------------------------------------------------------------------
// Kernel 0: W -> g_Wh (half, transposed, c interleave-32).
// ---------------------------------------------------------------------------
__global__ void transpose_w(const float* __restrict__ Wk, const float* __restrict__ Wv) {
    __shared__ float t[32][33];
    const int n0 = blockIdx.x * 32;
    const int c0 = blockIdx.y * 32;
    const float* W = (blockIdx.x < 4) ? Wk : Wv;
    const int nb = (blockIdx.x & 3) * 32;
    for (int r = threadIdx.y; r < 32; r += 8)
        t[r][threadIdx.x] = W[(size_t)(c0 + r) * HD + nb + threadIdx.x];
    __syncthreads();
    for (int r = threadIdx.y; r < 32; r += 8) {
        int c = c0 + threadIdx.x;
        int cs = (c & ~31) + pos32(c & 31);
        g_Wh[(size_t)(n0 + r) * EMB + cs] = __float2half(t[threadIdx.x][r]);
    }
}

// ---------------------------------------------------------------------------
// Kernel 1: projection. C[128m x 128n] = x_tile @ W(wsel). 256 thr, 2 CTAs/SM.
// grid (2, 128), blockIdx.x = wsel (K/V pair shares x via L2).
// ---------------------------------------------------------------------------
#define PJ_AB   32768
#define PJ_ST   (32768 + 16384)     // 49152
#define PJ_SMEM (2 * PJ_ST)         // 98304

__global__ __launch_bounds__(256, 2) void proj_kernel(const float* __restrict__ x) {
    extern __shared__ char smc[];
    const int tid = threadIdx.x, w = tid >> 5, lane = tid & 31;
    const int gid = lane >> 2, tig = lane & 3;
    const int wm = w & 3, wn = w >> 2;
    const int wsel = blockIdx.x;
    const int m0 = blockIdx.y * 128;
    const int swadd = 4 * (gid & 3);          // A-tile swizzle (float2 units)
    const int gB = tig + 4 * (gid & 1);       // B-tile granule base

    float acc[16][4];
#pragma unroll
    for (int t = 0; t < 16; t++)
#pragma unroll
        for (int v = 0; v < 4; v++) acc[t][v] = 0.0f;

    auto issue = [&](int st, int c) {
        char* As = smc + st * PJ_ST;
        char* Bs = As + PJ_AB;
#pragma unroll
        for (int q = 0; q < 8; q++) {     // A: 128 rows x 256B, swizzled 16B segs
            int f = q * 256 + tid, r = f >> 4, m = f & 15;
            cp16(As + r * 256 + (((m + 2 * (r & 3)) & 15) << 4),
                 &x[(size_t)(m0 + r) * EMB + c * 64 + m * 4]);
        }
#pragma unroll
        for (int q = 0; q < 4; q++) {     // B: 128 rows x 128B (halves)
            int f = q * 256 + tid, r = f >> 3, m = f & 7;
            cp16(Bs + r * 128 + (((m + 4 * (r & 1)) & 7) << 4),
                 &g_Wh[(size_t)(wsel * 128 + r) * EMB + c * 64 + m * 8]);
        }
    };

    issue(0, 0); CP_COMMIT();

    for (int c = 0; c < 16; c++) {
        if (c + 1 < 16) issue((c + 1) & 1, c + 1);
        CP_COMMIT();
        cp_wait<1>();
        __syncthreads();

        const float* As = (const float*)(smc + (c & 1) * PJ_ST);
        const char* Bs = smc + (c & 1) * PJ_ST + PJ_AB;
#pragma unroll
        for (int ks2 = 0; ks2 < 2; ks2++) {
            uint32_t a[2][2][4];          // [kk][mi][frag]
#pragma unroll
            for (int kk = 0; kk < 2; kk++) {
                const int ks = 2 * ks2 + kk;
                const int ulo = (8 * ks + tig + swadd) & 31;
                const int uhi = (8 * ks + tig + 4 + swadd) & 31;
#pragma unroll
                for (int mi = 0; mi < 2; mi++) {
                    int r = 32 * wm + 16 * mi + gid;
                    float2 lo0 = *(const float2*)(As + r * 64 + ulo * 2);
                    float2 lo1 = *(const float2*)(As + (r + 8) * 64 + ulo * 2);
                    float2 hi0 = *(const float2*)(As + r * 64 + uhi * 2);
                    float2 hi1 = *(const float2*)(As + (r + 8) * 64 + uhi * 2);
                    a[kk][mi][0] = packh2(lo0.x, lo0.y);
                    a[kk][mi][1] = packh2(lo1.x, lo1.y);
                    a[kk][mi][2] = packh2(hi0.x, hi0.y);
                    a[kk][mi][3] = packh2(hi1.x, hi1.y);
                }
            }
#pragma unroll
            for (int ni = 0; ni < 8; ni++) {
                int rB = 64 * wn + 8 * ni + gid;
                int g = (4 * ks2 + gB) & 7;
                uint4 bb = *(const uint4*)(Bs + rB * 128 + g * 16);
                mma16(acc[ni],     a[0][0], bb.x, bb.y);
                mma16(acc[8 + ni], a[0][1], bb.x, bb.y);
                mma16(acc[ni],     a[1][0], bb.z, bb.w);
                mma16(acc[8 + ni], a[1][1], bb.z, bb.w);
            }
        }
        __syncthreads();
    }

    if (wsel == 0) {
        // g_Kh scaled by KSCALE, h interleave-32
#pragma unroll
        for (int mi = 0; mi < 2; mi++) {
            int r0 = m0 + 32 * wm + 16 * mi + gid;
#pragma unroll
            for (int ni = 0; ni < 8; ni++) {
                int n = 64 * wn + 8 * ni + 2 * tig;
                int hst = (n & ~31) + pos32(n & 31);
                float* ac = acc[mi * 8 + ni];
                *(__half2*)&g_Kh[(size_t)r0 * HD + hst] =
                    __floats2half2_rn(ac[0] * KSCALE, ac[1] * KSCALE);
                *(__half2*)&g_Kh[(size_t)(r0 + 8) * HD + hst] =
                    __floats2half2_rn(ac[2] * KSCALE, ac[3] * KSCALE);
            }
        }
    } else {
        // V^T via smem staging [h=128][t=128 pad 136], token interleave-32
        __half* vs = (__half*)smc;
#pragma unroll
        for (int mi = 0; mi < 2; mi++) {
            int tl = 32 * wm + 16 * mi + gid;
            int ts0 = (tl & ~31) + pos32(tl & 31);
            int ts1 = ts0 + 2;                   // pos32((tl+8)&31) = pos32+2
#pragma unroll
            for (int ni = 0; ni < 8; ni++) {
                int h0 = 64 * wn + 8 * ni + 2 * tig;
                float* ac = acc[mi * 8 + ni];
                vs[h0 * 136 + ts0]       = __float2half(ac[0]);
                vs[(h0 + 1) * 136 + ts0] = __float2half(ac[1]);
                vs[h0 * 136 + ts1]       = __float2half(ac[2]);
                vs[(h0 + 1) * 136 + ts1] = __float2half(ac[3]);
            }
        }
        __syncthreads();
        const int bb = m0 >> 11;
        const int tb = m0 & 2047;
        __half* dst = g_Vth + (size_t)bb * HD * SEQ;
#pragma unroll
        for (int q = 0; q < 8; q++) {
            int f = q * 256 + tid, r = f >> 4, m = f & 15;
            uint4 v = *(uint4*)&vs[r * 136 + m * 8];
            *(uint4*)&dst[(size_t)r * SEQ + tb + m * 8] = v;
        }
    }
}

// ---------------------------------------------------------------------------
// Kernel 2: attention + fused combine. PERSISTENT: 444 CTAs x 128 thr, 3/SM,
// atomic work queue over 640 items; K/V double-buffer runs continuously
// across items (next item's first tile staged during current item's last).
// ---------------------------------------------------------------------------
#define AT_SMEM 65536

__global__ __launch_bounds__(128, 3) void attn_kernel(float* __restrict__ out) {
    extern __shared__ char smc[];
    __shared__ int s_item;
    const int tid = threadIdx.x, w = tid >> 5, lane = tid & 31;
    const int gid = lane >> 2, tig = lane & 3;
    const int gswK = tig + 4 * (gid & 3);    // K frag granule base (mod 16)
    const int gswV = tig + 4 * (gid & 1);    // V frag granule base (mod 8)
    const uint32_t bones = (gid == 0) ? 0x3C003C00u : 0u;   // ones column B frag

    auto stagef = [&](int bb, int jj, int bsel) {
        const __half* Kb  = g_Kh  + (size_t)bb * SEQ * HD;
        const __half* Vtb = g_Vth + (size_t)bb * HD * SEQ;
        const int tok0 = jj * 64;
        char* Ks = smc + bsel * 16384;
        char* Vs = smc + 32768 + bsel * 16384;
#pragma unroll
        for (int q = 0; q < 8; q++) {          // K: 64 rows x 256B
            int f = q * 128 + tid, r = f >> 4, m = f & 15;
            cp16(Ks + r * 256 + (((m + 4 * (r & 3)) & 15) << 4),
                 &Kb[(size_t)(tok0 + r) * HD + m * 8]);
        }
#pragma unroll
        for (int q = 0; q < 8; q++) {          // V: 128 rows x 128B
            int f = q * 128 + tid, r = f >> 3, m = f & 7;
            cp16(Vs + r * 128 + (((m + 4 * (r & 1)) & 7) << 4),
                 &Vtb[(size_t)r * SEQ + tok0 + m * 8]);
        }
    };

    // pop first item
    if (tid == 0) s_item = atomicAdd(&g_qhead, 1);
    __syncthreads();
    int cur = s_item;
    if (cur >= N_ATTN) return;

    int tc = 0;   // global tile counter -> buffer parity
    stagef(cur & 7, 8 * ITEM_CH[cur >> 3], 0);
    CP_COMMIT();

    for (;;) {
        const int b = cur & 7, idx = cur >> 3;
        const int qt = ITEM_QT[idx], ch = ITEM_CH[idx];
        const int jbeg = 8 * ch;
        const int jend = min(8 * ch + 8, qt + 1);
        const int nch = (qt >> 3) + 1;

        const __half* Kbh = g_Kh + (size_t)b * SEQ * HD;

        // Q fragments from gmem via LDG.128 (q = key(x) source bug: read g_Kh)
        const int qrow = qt * 64 + 16 * w + gid;
        const uint4* Qg0 = (const uint4*)(Kbh + (size_t)qrow * HD);
        const uint4* Qg8 = (const uint4*)(Kbh + (size_t)(qrow + 8) * HD);
        uint32_t qa[8][4];
#pragma unroll
        for (int ks2 = 0; ks2 < 4; ks2++) {
            uint4 u0 = Qg0[4 * ks2 + tig];
            uint4 u1 = Qg8[4 * ks2 + tig];
            qa[2 * ks2][0]     = u0.x; qa[2 * ks2][2]     = u0.y;
            qa[2 * ks2 + 1][0] = u0.z; qa[2 * ks2 + 1][2] = u0.w;
            qa[2 * ks2][1]     = u1.x; qa[2 * ks2][3]     = u1.y;
            qa[2 * ks2 + 1][1] = u1.z; qa[2 * ks2 + 1][3] = u1.w;
        }

        float o[16][4];
#pragma unroll
        for (int t = 0; t < 16; t++)
#pragma unroll
            for (int v = 0; v < 4; v++) o[t][v] = 0.0f;
        float ol[4] = {0.f, 0.f, 0.f, 0.f};

        const int qr0 = qt * 64 + 16 * w;
        int nxt = N_ATTN;

        for (int jj = jbeg; jj < jend; jj++) {
            if (jj + 1 < jend) {
                stagef(b, jj + 1, (tc + 1) & 1);
            } else {
                if (tid == 0) s_item = atomicAdd(&g_qhead, 1);
                __syncthreads();
                nxt = s_item;
                if (nxt < N_ATTN)
                    stagef(nxt & 7, 8 * ITEM_CH[nxt >> 3], (tc + 1) & 1);
            }
            CP_COMMIT();
            cp_wait<1>();
            __syncthreads();

            const char* Ks = smc + (tc & 1) * 16384;
            const char* Vs = smc + 32768 + (tc & 1) * 16384;

            // ---- S' = QK^T (pre-scaled, log2e folded) ----
            float s[8][4];
#pragma unroll
            for (int t = 0; t < 8; t++)
#pragma unroll
                for (int v = 0; v < 4; v++) s[t][v] = 0.0f;

#pragma unroll
            for (int ks2 = 0; ks2 < 4; ks2++) {
                const int g = ((4 * ks2 + gswK) & 15) << 4;
#pragma unroll
                for (int t = 0; t < 8; t++) {
                    uint4 bb = *(const uint4*)(Ks + (8 * t + gid) * 256 + g);
                    mma16(s[t], qa[2 * ks2],     bb.x, bb.y);
                    mma16(s[t], qa[2 * ks2 + 1], bb.z, bb.w);
                }
            }

            // ---- causal mask (diag tile only), P = ex2(S') in f16x2 ----
            if (jj == qt) {
                const int kv0 = jj * 64;
                const int r0 = qr0 + gid, r1 = r0 + 8;
#pragma unroll
                for (int t = 0; t < 8; t++) {
                    const int col = kv0 + 8 * t + 2 * tig;
                    if (col > r0)     s[t][0] = -1e30f;
                    if (col + 1 > r0) s[t][1] = -1e30f;
                    if (col > r1)     s[t][2] = -1e30f;
                    if (col + 1 > r1) s[t][3] = -1e30f;
                }
            }
            uint32_t e[8][2];
#pragma unroll
            for (int t = 0; t < 8; t++) {
                e[t][0] = ex2h2(packh2(s[t][0], s[t][1]));
                e[t][1] = ex2h2(packh2(s[t][2], s[t][3]));
            }

            // ---- O += P V ; l += P @ ones ----
#pragma unroll
            for (int ks2 = 0; ks2 < 2; ks2++) {
                uint32_t alo[4], ahi[4];
                alo[0] = e[4 * ks2][0];     alo[1] = e[4 * ks2][1];
                alo[2] = e[4 * ks2 + 1][0]; alo[3] = e[4 * ks2 + 1][1];
                ahi[0] = e[4 * ks2 + 2][0]; ahi[1] = e[4 * ks2 + 2][1];
                ahi[2] = e[4 * ks2 + 3][0]; ahi[3] = e[4 * ks2 + 3][1];
                mma16(ol, alo, bones, bones);
                mma16(ol, ahi, bones, bones);
                const int g = ((4 * ks2 + gswV) & 7) << 4;
#pragma unroll
                for (int t = 0; t < 16; t++) {
                    uint4 bb = *(const uint4*)(Vs + (8 * t + gid) * 128 + g);
                    mma16(o[t], alo, bb.x, bb.y);
                    mma16(o[t], ahi, bb.z, bb.w);
                }
            }
            tc++;
            __syncthreads();
        }

        // broadcast row sums from quad leader (col 0 -> tig==0's d0/d2)
        const float l0 = __shfl_sync(0xffffffffu, ol[0], lane & ~3);
        const float l1 = __shfl_sync(0xffffffffu, ol[2], lane & ~3);

        const int row0 = qt * 64 + 16 * w + gid;
        if (nch == 1) {
            const float i0 = 1.0f / l0, i1 = 1.0f / l1;
#pragma unroll
            for (int t = 0; t < 16; t++) {
                int h = 8 * t + 2 * tig;
                *(float2*)&out[((size_t)b * SEQ + row0) * HD + h] =
                    make_float2(o[t][0] * i0, o[t][1] * i0);
                *(float2*)&out[((size_t)b * SEQ + row0 + 8) * HD + h] =
                    make_float2(o[t][2] * i1, o[t][3] * i1);
            }
        } else {
            float* Op = g_Opart + (size_t)ch * BATCH * SEQ * HD;
#pragma unroll
            for (int t = 0; t < 16; t++) {
                int h = 8 * t + 2 * tig;
                *(float2*)&Op[((size_t)b * SEQ + row0) * HD + h]     = make_float2(o[t][0], o[t][1]);
                *(float2*)&Op[((size_t)b * SEQ + row0 + 8) * HD + h] = make_float2(o[t][2], o[t][3]);
            }
            if (tig == 0) {
                g_lpart[ch * BATCH * SEQ + b * SEQ + row0]     = l0;
                g_lpart[ch * BATCH * SEQ + b * SEQ + row0 + 8] = l1;
            }
            __threadfence();
            __syncthreads();
            __shared__ int s_last;
            if (tid == 0) {
                int old = atomicAdd(&g_cnt[b * 32 + qt], 1);
                s_last = (old == nch - 1) ? 1 : 0;
            }
            __syncthreads();
            if (s_last) {
                __threadfence();
#pragma unroll 4
                for (int u = 0; u < 16; u++) {
                    int flat = u * 128 + tid;
                    int c4 = flat & 31, rl = flat >> 5;
                    size_t row = (size_t)b * SEQ + qt * 64 + rl;
                    float l = 0.0f;
                    float4 o4 = make_float4(0.f, 0.f, 0.f, 0.f);
                    for (int c = 0; c < nch; c++) {
                        l += g_lpart[c * BATCH * SEQ + row];
                        float4 v = *(const float4*)&g_Opart[(size_t)c * BATCH * SEQ * HD + row * HD + c4 * 4];
                        o4.x += v.x; o4.y += v.y; o4.z += v.z; o4.w += v.w;
                    }
                    float inv = 1.0f / l;
                    *(float4*)&out[row * HD + c4 * 4] =
                        make_float4(o4.x * inv, o4.y * inv, o4.z * inv, o4.w * inv);
                }
            }
        }

        if (nxt >= N_ATTN) return;
        cur = nxt;
    }
}

// ---------------------------------------------------------------------------
extern "C" void kernel_launch(void* const* d_in, const int* in_sizes, int n_in,
                              void* d_out, int out_size)
{
    const float* x  = (const float*)d_in[0];
    const float* Wk = (const float*)d_in[1];
    // d_in[2] = W_query: intentionally unused (reference uses W_key for q too)
    const float* Wv = (const float*)d_in[3];
    float* out = (float*)d_out;

    cudaFuncSetAttribute(proj_kernel, cudaFuncAttributeMaxDynamicSharedMemorySize, PJ_SMEM);
    cudaFuncSetAttribute(attn_kernel, cudaFuncAttributeMaxDynamicSharedMemorySize, AT_SMEM);

    reset_kernel<<<1, 256>>>();
    transpose_w<<<dim3(8, 32), dim3(32, 8)>>>(Wk, Wv);
    proj_kernel<<<dim3(2, 128), 256, PJ_SMEM>>>(x);     // merged K/V; x shared via L2
    attn_kernel<<<444, 128, AT_SMEM>>>(out);            // persistent + work-stealing
}

// round 15
// speedup vs baseline: 1.0482x; 1.0482x over previous
#include <cuda_runtime.h>
#include <cuda_fp16.h>
#include <cstdint>

#define BATCH 8
#define SEQ   2048
#define EMB   1024
#define HD    128

// K pre-scale: sqrt(HD^-0.5 * log2(e)) — K is also Q, so MMA yields S*scale*log2e.
#define KSCALE 0.35709512f

// ---------------- scratch (allocation-free rule) ----------------
__device__ __half g_Kh [BATCH * SEQ * HD];       // K(scaled), fp16, h interleave-32
__device__ __half g_Vth[BATCH * HD * SEQ];       // V^T [b][h][t], fp16, t interleave-32
__device__ __half g_Wh [2 * HD * EMB];           // [Wk^T;Wv^T] [256][1024], c interleave-32
__device__ float  g_Opart[4 * BATCH * SEQ * HD]; // per-chunk unnormalized O
__device__ float  g_lpart[4 * BATCH * SEQ];      // per-chunk row sums
__device__ int    g_cnt[BATCH * 32];             // per (b, qt64) finished-chunk counters

// Attn items: (qt, ch), q-tile = 64 rows, chunk = kv64 tiles [8ch, min(8ch+8, qt+1)).
__constant__ unsigned char ITEM_QT[80] = {
    31,31,31,31,
    30,30,30, 29,29,29, 28,28,28, 27,27,27, 26,26,26, 25,25,25, 24,24,24, 23,23,23,
    22,22, 21,21, 20,20, 19,19, 18,18, 17,17, 16,16, 15,15,
    14, 13, 12, 11, 10, 9, 8, 7,
    30,22,14,6, 29,21,13,5, 28,20,12,4, 27,19,11,3, 26,18,10,2, 25,17,9,1, 24,16,8,0 };
__constant__ unsigned char ITEM_CH[80] = {
    0,1,2,3,
    0,1,2, 0,1,2, 0,1,2, 0,1,2, 0,1,2, 0,1,2, 0,1,2, 0,1,2,
    0,1, 0,1, 0,1, 0,1, 0,1, 0,1, 0,1, 0,1,
    0, 0, 0, 0, 0, 0, 0, 0,
    3,2,1,0, 3,2,1,0, 3,2,1,0, 3,2,1,0, 3,2,1,0, 3,2,1,0, 3,2,1,0 };

// ---------------- helpers ----------------
__device__ __forceinline__ void cp16(void* s, const void* g) {
    asm volatile("cp.async.cg.shared.global [%0], [%1], 16;"
                 :: "r"((uint32_t)__cvta_generic_to_shared(s)), "l"(g));
}
#define CP_COMMIT() asm volatile("cp.async.commit_group;" ::: "memory")
template <int N>
__device__ __forceinline__ void cp_wait() {
    asm volatile("cp.async.wait_group %0;" :: "n"(N) : "memory");
}
__device__ __forceinline__ uint32_t packh2(float lo, float hi) {
    uint32_t d;
    asm("cvt.rn.f16x2.f32 %0, %1, %2;" : "=r"(d) : "f"(hi), "f"(lo));
    return d;
}
__device__ __forceinline__ uint32_t ex2h2(uint32_t a) {
    uint32_t d;
    asm("ex2.approx.f16x2 %0, %1;" : "=r"(d) : "r"(a));
    return d;
}
__device__ __forceinline__ float2 h2f2(uint32_t h) {
    float2 f;
    asm("cvt.f32.f16 %0, %2;\n\tmov.b32 {%2, %2}, %2;" : : );   // placeholder avoided
    // use intrinsic instead:
    __half2 hh = *reinterpret_cast<__half2*>(&h);
    f = __half22float2(hh);
    return f;
}
__device__ __forceinline__ void mma16(float* d, const uint32_t* a, uint32_t b0, uint32_t b1) {
    asm volatile("mma.sync.aligned.m16n8k16.row.col.f32.f16.f16.f32 "
        "{%0,%1,%2,%3}, {%4,%5,%6,%7}, {%8,%9}, {%0,%1,%2,%3};"
        : "+f"(d[0]), "+f"(d[1]), "+f"(d[2]), "+f"(d[3])
        : "r"(a[0]), "r"(a[1]), "r"(a[2]), "r"(a[3]), "r"(b0), "r"(b1));
}
// interleave-32: 16B granule g holds logical cols {2g,2g+1,2g+8,2g+9,2g+16,2g+17,2g+24,2g+25}
__device__ __forceinline__ int pos32(int c) {
    return 8 * ((c & 7) >> 1) + (c & 1) + 2 * ((c >> 3) & 1) + 4 * ((c >> 4) & 1);
}

// ---------------------------------------------------------------------------
// Kernel 0: W -> g_Wh (half, transposed, c interleave-32) + reset counters.
// ---------------------------------------------------------------------------
__global__ void transpose_w(const float* __restrict__ Wk, const float* __restrict__ Wv) {
    __shared__ float t[32][33];
    if (blockIdx.x == 0 && blockIdx.y == 0) {
        int f = threadIdx.y * 32 + threadIdx.x;
        if (f < BATCH * 32) g_cnt[f] = 0;
    }
    const int n0 = blockIdx.x * 32;
    const int c0 = blockIdx.y * 32;
    const float* W = (blockIdx.x < 4) ? Wk : Wv;
    const int nb = (blockIdx.x & 3) * 32;
    for (int r = threadIdx.y; r < 32; r += 8)
        t[r][threadIdx.x] = W[(size_t)(c0 + r) * HD + nb + threadIdx.x];
    __syncthreads();
    for (int r = threadIdx.y; r < 32; r += 8) {
        int c = c0 + threadIdx.x;
        int cs = (c & ~31) + pos32(c & 31);
        g_Wh[(size_t)(n0 + r) * EMB + cs] = __float2half(t[threadIdx.x][r]);
    }
}

// ---------------------------------------------------------------------------
// Kernel 1: projection. C[128m x 128n] = x_tile @ W(wsel). 256 thr, 2 CTAs/SM.
// grid (2, 128), blockIdx.x = wsel (K/V pair shares x via L2).
// ---------------------------------------------------------------------------
#define PJ_AB   32768
#define PJ_ST   (32768 + 16384)     // 49152
#define PJ_SMEM (2 * PJ_ST)         // 98304

__global__ __launch_bounds__(256, 2) void proj_kernel(const float* __restrict__ x) {
    extern __shared__ char smc[];
    const int tid = threadIdx.x, w = tid >> 5, lane = tid & 31;
    const int gid = lane >> 2, tig = lane & 3;
    const int wm = w & 3, wn = w >> 2;
    const int wsel = blockIdx.x;
    const int m0 = blockIdx.y * 128;
    const int swadd = 4 * (gid & 3);          // A-tile swizzle (float2 units)
    const int gB = tig + 4 * (gid & 1);       // B-tile granule base

    float acc[16][4];
#pragma unroll
    for (int t = 0; t < 16; t++)
#pragma unroll
        for (int v = 0; v < 4; v++) acc[t][v] = 0.0f;

    auto issue = [&](int st, int c) {
        char* As = smc + st * PJ_ST;
        char* Bs = As + PJ_AB;
#pragma unroll
        for (int q = 0; q < 8; q++) {     // A: 128 rows x 256B, swizzled 16B segs
            int f = q * 256 + tid, r = f >> 4, m = f & 15;
            cp16(As + r * 256 + (((m + 2 * (r & 3)) & 15) << 4),
                 &x[(size_t)(m0 + r) * EMB + c * 64 + m * 4]);
        }
#pragma unroll
        for (int q = 0; q < 4; q++) {     // B: 128 rows x 128B (halves)
            int f = q * 256 + tid, r = f >> 3, m = f & 7;
            cp16(Bs + r * 128 + (((m + 4 * (r & 1)) & 7) << 4),
                 &g_Wh[(size_t)(wsel * 128 + r) * EMB + c * 64 + m * 8]);
        }
    };

    issue(0, 0); CP_COMMIT();

    for (int c = 0; c < 16; c++) {
        if (c + 1 < 16) issue((c + 1) & 1, c + 1);
        CP_COMMIT();
        cp_wait<1>();
        __syncthreads();

        const float* As = (const float*)(smc + (c & 1) * PJ_ST);
        const char* Bs = smc + (c & 1) * PJ_ST + PJ_AB;
#pragma unroll
        for (int ks2 = 0; ks2 < 2; ks2++) {
            uint32_t a[2][2][4];          // [kk][mi][frag]
#pragma unroll
            for (int kk = 0; kk < 2; kk++) {
                const int ks = 2 * ks2 + kk;
                const int ulo = (8 * ks + tig + swadd) & 31;
                const int uhi = (8 * ks + tig + 4 + swadd) & 31;
#pragma unroll
                for (int mi = 0; mi < 2; mi++) {
                    int r = 32 * wm + 16 * mi + gid;
                    float2 lo0 = *(const float2*)(As + r * 64 + ulo * 2);
                    float2 lo1 = *(const float2*)(As + (r + 8) * 64 + ulo * 2);
                    float2 hi0 = *(const float2*)(As + r * 64 + uhi * 2);
                    float2 hi1 = *(const float2*)(As + (r + 8) * 64 + uhi * 2);
                    a[kk][mi][0] = packh2(lo0.x, lo0.y);
                    a[kk][mi][1] = packh2(lo1.x, lo1.y);
                    a[kk][mi][2] = packh2(hi0.x, hi0.y);
                    a[kk][mi][3] = packh2(hi1.x, hi1.y);
                }
            }
#pragma unroll
            for (int ni = 0; ni < 8; ni++) {
                int rB = 64 * wn + 8 * ni + gid;
                int g = (4 * ks2 + gB) & 7;
                uint4 bb = *(const uint4*)(Bs + rB * 128 + g * 16);
                mma16(acc[ni],     a[0][0], bb.x, bb.y);
                mma16(acc[8 + ni], a[0][1], bb.x, bb.y);
                mma16(acc[ni],     a[1][0], bb.z, bb.w);
                mma16(acc[8 + ni], a[1][1], bb.z, bb.w);
            }
        }
        __syncthreads();
    }

    if (wsel == 0) {
        // g_Kh scaled by KSCALE, h interleave-32
#pragma unroll
        for (int mi = 0; mi < 2; mi++) {
            int r0 = m0 + 32 * wm + 16 * mi + gid;
#pragma unroll
            for (int ni = 0; ni < 8; ni++) {
                int n = 64 * wn + 8 * ni + 2 * tig;
                int hst = (n & ~31) + pos32(n & 31);
                float* ac = acc[mi * 8 + ni];
                *(__half2*)&g_Kh[(size_t)r0 * HD + hst] =
                    __floats2half2_rn(ac[0] * KSCALE, ac[1] * KSCALE);
                *(__half2*)&g_Kh[(size_t)(r0 + 8) * HD + hst] =
                    __floats2half2_rn(ac[2] * KSCALE, ac[3] * KSCALE);
            }
        }
    } else {
        // V^T via smem staging [h=128][t=128 pad 136], token interleave-32
        __half* vs = (__half*)smc;
#pragma unroll
        for (int mi = 0; mi < 2; mi++) {
            int tl = 32 * wm + 16 * mi + gid;
            int ts0 = (tl & ~31) + pos32(tl & 31);
            int ts1 = ts0 + 2;                   // pos32((tl+8)&31) = pos32+2
#pragma unroll
            for (int ni = 0; ni < 8; ni++) {
                int h0 = 64 * wn + 8 * ni + 2 * tig;
                float* ac = acc[mi * 8 + ni];
                vs[h0 * 136 + ts0]       = __float2half(ac[0]);
                vs[(h0 + 1) * 136 + ts0] = __float2half(ac[1]);
                vs[h0 * 136 + ts1]       = __float2half(ac[2]);
                vs[(h0 + 1) * 136 + ts1] = __float2half(ac[3]);
            }
        }
        __syncthreads();
        const int bb = m0 >> 11;
        const int tb = m0 & 2047;
        __half* dst = g_Vth + (size_t)bb * HD * SEQ;
#pragma unroll
        for (int q = 0; q < 8; q++) {
            int f = q * 256 + tid, r = f >> 4, m = f & 15;
            uint4 v = *(uint4*)&vs[r * 136 + m * 8];
            *(uint4*)&dst[(size_t)r * SEQ + tb + m * 8] = v;
        }
    }
}

// ---------------------------------------------------------------------------
// Kernel 2: attention + fused combine. 128 threads, 64 q-rows, chunk = 8 kv64
// tiles, 3 CTAs/SM. Softmax in f16x2; row sums on fma pipe (tensor-rate probe).
// ---------------------------------------------------------------------------
#define AT_SMEM 65536

__global__ __launch_bounds__(128, 3) void attn_kernel(float* __restrict__ out) {
    extern __shared__ char smc[];
    const int tid = threadIdx.x, w = tid >> 5, lane = tid & 31;
    const int gid = lane >> 2, tig = lane & 3;
    const int b = blockIdx.x;
    const int qt = ITEM_QT[blockIdx.y];
    const int ch = ITEM_CH[blockIdx.y];
    const int jbeg = 8 * ch;
    const int jend = min(8 * ch + 8, qt + 1);
    const int nch = (qt >> 3) + 1;
    const int gswK = tig + 4 * (gid & 3);    // K frag granule base (mod 16)
    const int gswV = tig + 4 * (gid & 1);    // V frag granule base (mod 8)

    const __half* Kbh  = g_Kh  + (size_t)b * SEQ * HD;
    const __half* Vtbh = g_Vth + (size_t)b * HD * SEQ;

    auto stage = [&](int jj, int bsel) {
        const int tok0 = jj * 64;
        char* Ks = smc + bsel * 16384;
        char* Vs = smc + 32768 + bsel * 16384;
#pragma unroll
        for (int q = 0; q < 8; q++) {          // K: 64 rows x 256B
            int f = q * 128 + tid, r = f >> 4, m = f & 15;
            cp16(Ks + r * 256 + (((m + 4 * (r & 3)) & 15) << 4),
                 &Kbh[(size_t)(tok0 + r) * HD + m * 8]);
        }
#pragma unroll
        for (int q = 0; q < 8; q++) {          // V: 128 rows x 128B
            int f = q * 128 + tid, r = f >> 3, m = f & 7;
            cp16(Vs + r * 128 + (((m + 4 * (r & 1)) & 7) << 4),
                 &Vtbh[(size_t)r * SEQ + tok0 + m * 8]);
        }
    };

    stage(jbeg, 0); CP_COMMIT();

    // Q fragments from gmem via LDG.128 (q = key(x) source bug: read g_Kh)
    const int qrow = qt * 64 + 16 * w + gid;
    const uint4* Qg0 = (const uint4*)(Kbh + (size_t)qrow * HD);
    const uint4* Qg8 = (const uint4*)(Kbh + (size_t)(qrow + 8) * HD);
    uint32_t qa[8][4];
#pragma unroll
    for (int ks2 = 0; ks2 < 4; ks2++) {
        uint4 u0 = Qg0[4 * ks2 + tig];
        uint4 u1 = Qg8[4 * ks2 + tig];
        qa[2 * ks2][0]     = u0.x; qa[2 * ks2][2]     = u0.y;
        qa[2 * ks2 + 1][0] = u0.z; qa[2 * ks2 + 1][2] = u0.w;
        qa[2 * ks2][1]     = u1.x; qa[2 * ks2][3]     = u1.y;
        qa[2 * ks2 + 1][1] = u1.z; qa[2 * ks2 + 1][3] = u1.w;
    }

    float o[16][4];
#pragma unroll
    for (int t = 0; t < 16; t++)
#pragma unroll
        for (int v = 0; v < 4; v++) o[t][v] = 0.0f;
    float l0 = 0.0f, l1 = 0.0f;

    const int qr0 = qt * 64 + 16 * w;

    for (int jj = jbeg; jj < jend; jj++) {
        const int buf = (jj - jbeg) & 1;
        if (jj + 1 < jend) stage(jj + 1, buf ^ 1);
        CP_COMMIT();
        cp_wait<1>();
        __syncthreads();

        const char* Ks = smc + buf * 16384;
        const char* Vs = smc + 32768 + buf * 16384;

        // ---- S' = QK^T (pre-scaled, log2e folded): 16q x 64kv per warp ----
        float s[8][4];
#pragma unroll
        for (int t = 0; t < 8; t++)
#pragma unroll
            for (int v = 0; v < 4; v++) s[t][v] = 0.0f;

#pragma unroll
        for (int ks2 = 0; ks2 < 4; ks2++) {
            const int g = ((4 * ks2 + gswK) & 15) << 4;
#pragma unroll
            for (int t = 0; t < 8; t++) {
                uint4 bb = *(const uint4*)(Ks + (8 * t + gid) * 256 + g);
                mma16(s[t], qa[2 * ks2],     bb.x, bb.y);
                mma16(s[t], qa[2 * ks2 + 1], bb.z, bb.w);
            }
        }

        // ---- causal mask (diag tile only, in f32), then P = ex2(S') in f16x2 ----
        if (jj == qt) {
            const int kv0 = jj * 64;
            const int r0 = qr0 + gid, r1 = r0 + 8;
#pragma unroll
            for (int t = 0; t < 8; t++) {
                const int col = kv0 + 8 * t + 2 * tig;
                if (col > r0)     s[t][0] = -1e30f;
                if (col + 1 > r0) s[t][1] = -1e30f;
                if (col > r1)     s[t][2] = -1e30f;
                if (col + 1 > r1) s[t][3] = -1e30f;
            }
        }
        uint32_t e[8][2];
#pragma unroll
        for (int t = 0; t < 8; t++) {
            e[t][0] = ex2h2(packh2(s[t][0], s[t][1]));   // rows gid,   cols 8t+2tig..
            e[t][1] = ex2h2(packh2(s[t][2], s[t][3]));   // rows gid+8
        }

        // ---- row sums on fma pipe (probe: replaces 8 ones-column MMAs) ----
#pragma unroll
        for (int t = 0; t < 8; t++) {
            float2 u0 = __half22float2(*reinterpret_cast<__half2*>(&e[t][0]));
            float2 u1 = __half22float2(*reinterpret_cast<__half2*>(&e[t][1]));
            l0 += u0.x + u0.y;
            l1 += u1.x + u1.y;
        }

        // ---- O += P V (C-as-A packing; LDS.128 feeds 2 MMAs) ----
#pragma unroll
        for (int ks2 = 0; ks2 < 2; ks2++) {
            uint32_t alo[4], ahi[4];
            alo[0] = e[4 * ks2][0];     alo[1] = e[4 * ks2][1];
            alo[2] = e[4 * ks2 + 1][0]; alo[3] = e[4 * ks2 + 1][1];
            ahi[0] = e[4 * ks2 + 2][0]; ahi[1] = e[4 * ks2 + 2][1];
            ahi[2] = e[4 * ks2 + 3][0]; ahi[3] = e[4 * ks2 + 3][1];
            const int g = ((4 * ks2 + gswV) & 7) << 4;
#pragma unroll
            for (int t = 0; t < 16; t++) {
                uint4 bb = *(const uint4*)(Vs + (8 * t + gid) * 128 + g);
                mma16(o[t], alo, bb.x, bb.y);
                mma16(o[t], ahi, bb.z, bb.w);
            }
        }
        __syncthreads();
    }

    // quad-reduce row sums (tig lanes hold disjoint column subsets)
#pragma unroll
    for (int off = 1; off < 4; off <<= 1) {
        l0 += __shfl_xor_sync(0xffffffffu, l0, off);
        l1 += __shfl_xor_sync(0xffffffffu, l1, off);
    }

    const int row0 = qt * 64 + 16 * w + gid;
    if (nch == 1) {
        const float i0 = 1.0f / l0, i1 = 1.0f / l1;
#pragma unroll
        for (int t = 0; t < 16; t++) {
            int h = 8 * t + 2 * tig;
            *(float2*)&out[((size_t)b * SEQ + row0) * HD + h] =
                make_float2(o[t][0] * i0, o[t][1] * i0);
            *(float2*)&out[((size_t)b * SEQ + row0 + 8) * HD + h] =
                make_float2(o[t][2] * i1, o[t][3] * i1);
        }
    } else {
        float* Op = g_Opart + (size_t)ch * BATCH * SEQ * HD;
#pragma unroll
        for (int t = 0; t < 16; t++) {
            int h = 8 * t + 2 * tig;
            *(float2*)&Op[((size_t)b * SEQ + row0) * HD + h]     = make_float2(o[t][0], o[t][1]);
            *(float2*)&Op[((size_t)b * SEQ + row0 + 8) * HD + h] = make_float2(o[t][2], o[t][3]);
        }
        if (tig == 0) {
            g_lpart[ch * BATCH * SEQ + b * SEQ + row0]     = l0;
            g_lpart[ch * BATCH * SEQ + b * SEQ + row0 + 8] = l1;
        }
        __threadfence();
        __syncthreads();
        __shared__ int s_last;
        if (tid == 0) {
            int old = atomicAdd(&g_cnt[b * 32 + qt], 1);
            s_last = (old == nch - 1) ? 1 : 0;
        }
        __syncthreads();
        if (s_last) {
            __threadfence();
#pragma unroll 4
            for (int u = 0; u < 16; u++) {
                int flat = u * 128 + tid;
                int c4 = flat & 31, rl = flat >> 5;
                size_t row = (size_t)b * SEQ + qt * 64 + rl;
                float l = 0.0f;
                float4 o4 = make_float4(0.f, 0.f, 0.f, 0.f);
                for (int c = 0; c < nch; c++) {
                    l += g_lpart[c * BATCH * SEQ + row];
                    float4 v = *(const float4*)&g_Opart[(size_t)c * BATCH * SEQ * HD + row * HD + c4 * 4];
                    o4.x += v.x; o4.y += v.y; o4.z += v.z; o4.w += v.w;
                }
                float inv = 1.0f / l;
                *(float4*)&out[row * HD + c4 * 4] =
                    make_float4(o4.x * inv, o4.y * inv, o4.z * inv, o4.w * inv);
            }
        }
    }
}

// ---------------------------------------------------------------------------
extern "C" void kernel_launch(void* const* d_in, const int* in_sizes, int n_in,
                              void* d_out, int out_size)
{
    const float* x  = (const float*)d_in[0];
    const float* Wk = (const float*)d_in[1];
    // d_in[2] = W_query: intentionally unused (reference uses W_key for q too)
    const float* Wv = (const float*)d_in[3];
    float* out = (float*)d_out;

    cudaFuncSetAttribute(proj_kernel, cudaFuncAttributeMaxDynamicSharedMemorySize, PJ_SMEM);
    cudaFuncSetAttribute(attn_kernel, cudaFuncAttributeMaxDynamicSharedMemorySize, AT_SMEM);

    transpose_w<<<dim3(8, 32), dim3(32, 8)>>>(Wk, Wv);   // also resets counters
    proj_kernel<<<dim3(2, 128), 256, PJ_SMEM>>>(x);      // merged K/V; x shared via L2
    attn_kernel<<<dim3(8, 80), 128, AT_SMEM>>>(out);     // big items first
}

// round 16
// speedup vs baseline: 1.0518x; 1.0034x over previous
#include <cuda_runtime.h>
#include <cuda_fp16.h>
#include <cstdint>

#define BATCH 8
#define SEQ   2048
#define EMB   1024
#define HD    128

// K pre-scale: sqrt(HD^-0.5 * log2(e)) — K is also Q, so MMA yields S*scale*log2e.
#define KSCALE 0.35709512f

// ---------------- scratch (allocation-free rule) ----------------
__device__ __half g_Kh [BATCH * SEQ * HD];       // K(scaled), fp16, h interleave-32
__device__ __half g_Vth[BATCH * HD * SEQ];       // V^T [b][h][t], fp16, t interleave-32
__device__ __half g_Wh [2 * HD * EMB];           // [Wk^T;Wv^T] [256][1024], c interleave-32
__device__ float  g_Opart[4 * BATCH * SEQ * HD]; // per-chunk unnormalized O
__device__ float  g_lpart[4 * BATCH * SEQ];      // per-chunk row sums
__device__ int    g_cnt[BATCH * 32];             // per (b, qt64) finished-chunk counters

// Attn items: (qt, ch), q-tile = 64 rows, chunk = kv32 tiles [16ch, min(16ch+16, 2qt+2)).
__constant__ unsigned char ITEM_QT[80] = {
    31,31,31,31,
    30,30,30, 29,29,29, 28,28,28, 27,27,27, 26,26,26, 25,25,25, 24,24,24, 23,23,23,
    22,22, 21,21, 20,20, 19,19, 18,18, 17,17, 16,16, 15,15,
    14, 13, 12, 11, 10, 9, 8, 7,
    30,22,14,6, 29,21,13,5, 28,20,12,4, 27,19,11,3, 26,18,10,2, 25,17,9,1, 24,16,8,0 };
__constant__ unsigned char ITEM_CH[80] = {
    0,1,2,3,
    0,1,2, 0,1,2, 0,1,2, 0,1,2, 0,1,2, 0,1,2, 0,1,2, 0,1,2,
    0,1, 0,1, 0,1, 0,1, 0,1, 0,1, 0,1, 0,1,
    0, 0, 0, 0, 0, 0, 0, 0,
    3,2,1,0, 3,2,1,0, 3,2,1,0, 3,2,1,0, 3,2,1,0, 3,2,1,0, 3,2,1,0 };

// ---------------- helpers ----------------
__device__ __forceinline__ void cp16(void* s, const void* g) {
    asm volatile("cp.async.cg.shared.global [%0], [%1], 16;"
                 :: "r"((uint32_t)__cvta_generic_to_shared(s)), "l"(g));
}
#define CP_COMMIT() asm volatile("cp.async.commit_group;" ::: "memory")
template <int N>
__device__ __forceinline__ void cp_wait() {
    asm volatile("cp.async.wait_group %0;" :: "n"(N) : "memory");
}
__device__ __forceinline__ uint32_t packh2(float lo, float hi) {
    uint32_t d;
    asm("cvt.rn.f16x2.f32 %0, %1, %2;" : "=r"(d) : "f"(hi), "f"(lo));
    return d;
}
__device__ __forceinline__ uint32_t ex2h2(uint32_t a) {
    uint32_t d;
    asm("ex2.approx.f16x2 %0, %1;" : "=r"(d) : "r"(a));
    return d;
}
__device__ __forceinline__ void mma16(float* d, const uint32_t* a, uint32_t b0, uint32_t b1) {
    asm volatile("mma.sync.aligned.m16n8k16.row.col.f32.f16.f16.f32 "
        "{%0,%1,%2,%3}, {%4,%5,%6,%7}, {%8,%9}, {%0,%1,%2,%3};"
        : "+f"(d[0]), "+f"(d[1]), "+f"(d[2]), "+f"(d[3])
        : "r"(a[0]), "r"(a[1]), "r"(a[2]), "r"(a[3]), "r"(b0), "r"(b1));
}
// interleave-32: 16B granule g holds logical cols {2g,2g+1,2g+8,2g+9,2g+16,2g+17,2g+24,2g+25}
__device__ __forceinline__ int pos32(int c) {
    return 8 * ((c & 7) >> 1) + (c & 1) + 2 * ((c >> 3) & 1) + 4 * ((c >> 4) & 1);
}

// ---------------------------------------------------------------------------
// Kernel 0: W -> g_Wh (half, transposed, c interleave-32) + reset counters.
// ---------------------------------------------------------------------------
__global__ void transpose_w(const float* __restrict__ Wk, const float* __restrict__ Wv) {
    __shared__ float t[32][33];
    if (blockIdx.x == 0 && blockIdx.y == 0) {
        int f = threadIdx.y * 32 + threadIdx.x;
        if (f < BATCH * 32) g_cnt[f] = 0;
    }
    const int n0 = blockIdx.x * 32;
    const int c0 = blockIdx.y * 32;
    const float* W = (blockIdx.x < 4) ? Wk : Wv;
    const int nb = (blockIdx.x & 3) * 32;
    for (int r = threadIdx.y; r < 32; r += 8)
        t[r][threadIdx.x] = W[(size_t)(c0 + r) * HD + nb + threadIdx.x];
    __syncthreads();
    for (int r = threadIdx.y; r < 32; r += 8) {
        int c = c0 + threadIdx.x;
        int cs = (c & ~31) + pos32(c & 31);
        g_Wh[(size_t)(n0 + r) * EMB + cs] = __float2half(t[threadIdx.x][r]);
    }
}

// ---------------------------------------------------------------------------
// Kernel 1: projection. C[128m x 128n] = x_tile @ W(wsel). 256 thr, 2 CTAs/SM.
// grid (2, 128), blockIdx.x = wsel (K/V pair shares x via L2).
// ---------------------------------------------------------------------------
#define PJ_AB   32768
#define PJ_ST   (32768 + 16384)     // 49152
#define PJ_SMEM (2 * PJ_ST)         // 98304

__global__ __launch_bounds__(256, 2) void proj_kernel(const float* __restrict__ x) {
    extern __shared__ char smc[];
    const int tid = threadIdx.x, w = tid >> 5, lane = tid & 31;
    const int gid = lane >> 2, tig = lane & 3;
    const int wm = w & 3, wn = w >> 2;
    const int wsel = blockIdx.x;
    const int m0 = blockIdx.y * 128;
    const int swadd = 4 * (gid & 3);          // A-tile swizzle (float2 units)
    const int gB = tig + 4 * (gid & 1);       // B-tile granule base

    float acc[16][4];
#pragma unroll
    for (int t = 0; t < 16; t++)
#pragma unroll
        for (int v = 0; v < 4; v++) acc[t][v] = 0.0f;

    auto issue = [&](int st, int c) {
        char* As = smc + st * PJ_ST;
        char* Bs = As + PJ_AB;
#pragma unroll
        for (int q = 0; q < 8; q++) {     // A: 128 rows x 256B, swizzled 16B segs
            int f = q * 256 + tid, r = f >> 4, m = f & 15;
            cp16(As + r * 256 + (((m + 2 * (r & 3)) & 15) << 4),
                 &x[(size_t)(m0 + r) * EMB + c * 64 + m * 4]);
        }
#pragma unroll
        for (int q = 0; q < 4; q++) {     // B: 128 rows x 128B (halves)
            int f = q * 256 + tid, r = f >> 3, m = f & 7;
            cp16(Bs + r * 128 + (((m + 4 * (r & 1)) & 7) << 4),
                 &g_Wh[(size_t)(wsel * 128 + r) * EMB + c * 64 + m * 8]);
        }
    };

    issue(0, 0); CP_COMMIT();

    for (int c = 0; c < 16; c++) {
        if (c + 1 < 16) issue((c + 1) & 1, c + 1);
        CP_COMMIT();
        cp_wait<1>();
        __syncthreads();

        const float* As = (const float*)(smc + (c & 1) * PJ_ST);
        const char* Bs = smc + (c & 1) * PJ_ST + PJ_AB;
#pragma unroll
        for (int ks2 = 0; ks2 < 2; ks2++) {
            uint32_t a[2][2][4];          // [kk][mi][frag]
#pragma unroll
            for (int kk = 0; kk < 2; kk++) {
                const int ks = 2 * ks2 + kk;
                const int ulo = (8 * ks + tig + swadd) & 31;
                const int uhi = (8 * ks + tig + 4 + swadd) & 31;
#pragma unroll
                for (int mi = 0; mi < 2; mi++) {
                    int r = 32 * wm + 16 * mi + gid;
                    float2 lo0 = *(const float2*)(As + r * 64 + ulo * 2);
                    float2 lo1 = *(const float2*)(As + (r + 8) * 64 + ulo * 2);
                    float2 hi0 = *(const float2*)(As + r * 64 + uhi * 2);
                    float2 hi1 = *(const float2*)(As + (r + 8) * 64 + uhi * 2);
                    a[kk][mi][0] = packh2(lo0.x, lo0.y);
                    a[kk][mi][1] = packh2(lo1.x, lo1.y);
                    a[kk][mi][2] = packh2(hi0.x, hi0.y);
                    a[kk][mi][3] = packh2(hi1.x, hi1.y);
                }
            }
#pragma unroll
            for (int ni = 0; ni < 8; ni++) {
                int rB = 64 * wn + 8 * ni + gid;
                int g = (4 * ks2 + gB) & 7;
                uint4 bb = *(const uint4*)(Bs + rB * 128 + g * 16);
                mma16(acc[ni],     a[0][0], bb.x, bb.y);
                mma16(acc[8 + ni], a[0][1], bb.x, bb.y);
                mma16(acc[ni],     a[1][0], bb.z, bb.w);
                mma16(acc[8 + ni], a[1][1], bb.z, bb.w);
            }
        }
        __syncthreads();
    }

    if (wsel == 0) {
        // g_Kh scaled by KSCALE, h interleave-32
#pragma unroll
        for (int mi = 0; mi < 2; mi++) {
            int r0 = m0 + 32 * wm + 16 * mi + gid;
#pragma unroll
            for (int ni = 0; ni < 8; ni++) {
                int n = 64 * wn + 8 * ni + 2 * tig;
                int hst = (n & ~31) + pos32(n & 31);
                float* ac = acc[mi * 8 + ni];
                *(__half2*)&g_Kh[(size_t)r0 * HD + hst] =
                    __floats2half2_rn(ac[0] * KSCALE, ac[1] * KSCALE);
                *(__half2*)&g_Kh[(size_t)(r0 + 8) * HD + hst] =
                    __floats2half2_rn(ac[2] * KSCALE, ac[3] * KSCALE);
            }
        }
    } else {
        // V^T via smem staging [h=128][t=128 pad 136], token interleave-32
        __half* vs = (__half*)smc;
#pragma unroll
        for (int mi = 0; mi < 2; mi++) {
            int tl = 32 * wm + 16 * mi + gid;
            int ts0 = (tl & ~31) + pos32(tl & 31);
            int ts1 = ts0 + 2;                   // pos32((tl+8)&31) = pos32+2
#pragma unroll
            for (int ni = 0; ni < 8; ni++) {
                int h0 = 64 * wn + 8 * ni + 2 * tig;
                float* ac = acc[mi * 8 + ni];
                vs[h0 * 136 + ts0]       = __float2half(ac[0]);
                vs[(h0 + 1) * 136 + ts0] = __float2half(ac[1]);
                vs[h0 * 136 + ts1]       = __float2half(ac[2]);
                vs[(h0 + 1) * 136 + ts1] = __float2half(ac[3]);
            }
        }
        __syncthreads();
        const int bb = m0 >> 11;
        const int tb = m0 & 2047;
        __half* dst = g_Vth + (size_t)bb * HD * SEQ;
#pragma unroll
        for (int q = 0; q < 8; q++) {
            int f = q * 256 + tid, r = f >> 4, m = f & 15;
            uint4 v = *(uint4*)&vs[r * 136 + m * 8];
            *(uint4*)&dst[(size_t)r * SEQ + tb + m * 8] = v;
        }
    }
}

// ---------------------------------------------------------------------------
// Kernel 2: attention + fused combine. 128 threads, 64 q-rows, kv32 tiles,
// 4 CTAs/SM (32KB smem: K0@0 K1@8K V0@16K V1@24K). Softmax in f16x2.
// ---------------------------------------------------------------------------
#define AT_SMEM 32768

__global__ __launch_bounds__(128, 4) void attn_kernel(float* __restrict__ out) {
    extern __shared__ char smc[];
    const int tid = threadIdx.x, w = tid >> 5, lane = tid & 31;
    const int gid = lane >> 2, tig = lane & 3;
    const int b = blockIdx.x;
    const int qt = ITEM_QT[blockIdx.y];
    const int ch = ITEM_CH[blockIdx.y];
    const int jbeg = 16 * ch;                         // kv32 tile units
    const int jend = min(16 * ch + 16, 2 * qt + 2);
    const int nch = (qt >> 3) + 1;
    const int gswK = tig + 4 * (gid & 3);    // K frag granule base (mod 16)
    const int gswV = (tig + (gid & 3)) & 3;  // V frag granule (mod 4)

    const __half* Kbh  = g_Kh  + (size_t)b * SEQ * HD;
    const __half* Vtbh = g_Vth + (size_t)b * HD * SEQ;

    auto stage = [&](int jj, int bsel) {
        const int tok0 = jj * 32;
        char* Ks = smc + bsel * 8192;
        char* Vs = smc + 16384 + bsel * 8192;
#pragma unroll
        for (int q = 0; q < 4; q++) {          // K: 32 rows x 256B
            int f = q * 128 + tid, r = f >> 4, m = f & 15;
            cp16(Ks + r * 256 + (((m + 4 * (r & 3)) & 15) << 4),
                 &Kbh[(size_t)(tok0 + r) * HD + m * 8]);
        }
#pragma unroll
        for (int q = 0; q < 4; q++) {          // V: 128 rows x 64B
            int f = q * 128 + tid, r = f >> 2, m = f & 3;
            cp16(Vs + r * 64 + (((m + (r & 3)) & 3) << 4),
                 &Vtbh[(size_t)r * SEQ + tok0 + m * 8]);
        }
    };

    stage(jbeg, 0); CP_COMMIT();

    // Q fragments from gmem via LDG.128 (q = key(x) source bug: read g_Kh)
    const int qrow = qt * 64 + 16 * w + gid;
    const uint4* Qg0 = (const uint4*)(Kbh + (size_t)qrow * HD);
    const uint4* Qg8 = (const uint4*)(Kbh + (size_t)(qrow + 8) * HD);
    uint32_t qa[8][4];
#pragma unroll
    for (int ks2 = 0; ks2 < 4; ks2++) {
        uint4 u0 = Qg0[4 * ks2 + tig];
        uint4 u1 = Qg8[4 * ks2 + tig];
        qa[2 * ks2][0]     = u0.x; qa[2 * ks2][2]     = u0.y;
        qa[2 * ks2 + 1][0] = u0.z; qa[2 * ks2 + 1][2] = u0.w;
        qa[2 * ks2][1]     = u1.x; qa[2 * ks2][3]     = u1.y;
        qa[2 * ks2 + 1][1] = u1.z; qa[2 * ks2 + 1][3] = u1.w;
    }

    float o[16][4];
#pragma unroll
    for (int t = 0; t < 16; t++)
#pragma unroll
        for (int v = 0; v < 4; v++) o[t][v] = 0.0f;
    float l0 = 0.0f, l1 = 0.0f;

    const int qr0 = qt * 64 + 16 * w;

    for (int jj = jbeg; jj < jend; jj++) {
        const int buf = (jj - jbeg) & 1;
        if (jj + 1 < jend) stage(jj + 1, buf ^ 1);
        CP_COMMIT();
        cp_wait<1>();
        __syncthreads();

        const char* Ks = smc + buf * 8192;
        const char* Vs = smc + 16384 + buf * 8192;

        // ---- S' = QK^T (pre-scaled, log2e folded): 16q x 32kv per warp ----
        float s[4][4];
#pragma unroll
        for (int t = 0; t < 4; t++)
#pragma unroll
            for (int v = 0; v < 4; v++) s[t][v] = 0.0f;

#pragma unroll
        for (int ks2 = 0; ks2 < 4; ks2++) {
            const int g = ((4 * ks2 + gswK) & 15) << 4;
#pragma unroll
            for (int t = 0; t < 4; t++) {
                uint4 bb = *(const uint4*)(Ks + (8 * t + gid) * 256 + g);
                mma16(s[t], qa[2 * ks2],     bb.x, bb.y);
                mma16(s[t], qa[2 * ks2 + 1], bb.z, bb.w);
            }
        }

        // ---- causal mask (diag tiles only, f32), then P = ex2(S') in f16x2 ----
        if ((jj >> 1) == qt) {
            const int kv0 = jj * 32;
            const int r0 = qr0 + gid, r1 = r0 + 8;
#pragma unroll
            for (int t = 0; t < 4; t++) {
                const int col = kv0 + 8 * t + 2 * tig;
                if (col > r0)     s[t][0] = -1e30f;
                if (col + 1 > r0) s[t][1] = -1e30f;
                if (col > r1)     s[t][2] = -1e30f;
                if (col + 1 > r1) s[t][3] = -1e30f;
            }
        }
        uint32_t e[4][2];
#pragma unroll
        for (int t = 0; t < 4; t++) {
            e[t][0] = ex2h2(packh2(s[t][0], s[t][1]));   // rows gid
            e[t][1] = ex2h2(packh2(s[t][2], s[t][3]));   // rows gid+8
        }

        // ---- row sums on fma pipe ----
#pragma unroll
        for (int t = 0; t < 4; t++) {
            float2 u0 = __half22float2(*reinterpret_cast<__half2*>(&e[t][0]));
            float2 u1 = __half22float2(*reinterpret_cast<__half2*>(&e[t][1]));
            l0 += u0.x + u0.y;
            l1 += u1.x + u1.y;
        }

        // ---- O += P V : k-dim 32 = 2 k16 steps, one LDS.128 per V row ----
        {
            uint32_t alo[4], ahi[4];
            alo[0] = e[0][0]; alo[1] = e[0][1]; alo[2] = e[1][0]; alo[3] = e[1][1];
            ahi[0] = e[2][0]; ahi[1] = e[2][1]; ahi[2] = e[3][0]; ahi[3] = e[3][1];
            const int g = gswV << 4;
#pragma unroll
            for (int t = 0; t < 16; t++) {
                uint4 bb = *(const uint4*)(Vs + (8 * t + gid) * 64 + g);
                mma16(o[t], alo, bb.x, bb.y);
                mma16(o[t], ahi, bb.z, bb.w);
            }
        }
        __syncthreads();
    }

    // quad-reduce row sums
#pragma unroll
    for (int off = 1; off < 4; off <<= 1) {
        l0 += __shfl_xor_sync(0xffffffffu, l0, off);
        l1 += __shfl_xor_sync(0xffffffffu, l1, off);
    }

    const int row0 = qt * 64 + 16 * w + gid;
    if (nch == 1) {
        const float i0 = 1.0f / l0, i1 = 1.0f / l1;
#pragma unroll
        for (int t = 0; t < 16; t++) {
            int h = 8 * t + 2 * tig;
            *(float2*)&out[((size_t)b * SEQ + row0) * HD + h] =
                make_float2(o[t][0] * i0, o[t][1] * i0);
            *(float2*)&out[((size_t)b * SEQ + row0 + 8) * HD + h] =
                make_float2(o[t][2] * i1, o[t][3] * i1);
        }
    } else {
        float* Op = g_Opart + (size_t)ch * BATCH * SEQ * HD;
#pragma unroll
        for (int t = 0; t < 16; t++) {
            int h = 8 * t + 2 * tig;
            *(float2*)&Op[((size_t)b * SEQ + row0) * HD + h]     = make_float2(o[t][0], o[t][1]);
            *(float2*)&Op[((size_t)b * SEQ + row0 + 8) * HD + h] = make_float2(o[t][2], o[t][3]);
        }
        if (tig == 0) {
            g_lpart[ch * BATCH * SEQ + b * SEQ + row0]     = l0;
            g_lpart[ch * BATCH * SEQ + b * SEQ + row0 + 8] = l1;
        }
        __threadfence();
        __syncthreads();
        __shared__ int s_last;
        if (tid == 0) {
            int old = atomicAdd(&g_cnt[b * 32 + qt], 1);
            s_last = (old == nch - 1) ? 1 : 0;
        }
        __syncthreads();
        if (s_last) {
            __threadfence();
#pragma unroll 4
            for (int u = 0; u < 16; u++) {
                int flat = u * 128 + tid;
                int c4 = flat & 31, rl = flat >> 5;
                size_t row = (size_t)b * SEQ + qt * 64 + rl;
                float l = 0.0f;
                float4 o4 = make_float4(0.f, 0.f, 0.f, 0.f);
                for (int c = 0; c < nch; c++) {
                    l += g_lpart[c * BATCH * SEQ + row];
                    float4 v = *(const float4*)&g_Opart[(size_t)c * BATCH * SEQ * HD + row * HD + c4 * 4];
                    o4.x += v.x; o4.y += v.y; o4.z += v.z; o4.w += v.w;
                }
                float inv = 1.0f / l;
                *(float4*)&out[row * HD + c4 * 4] =
                    make_float4(o4.x * inv, o4.y * inv, o4.z * inv, o4.w * inv);
            }
        }
    }
}

// ---------------------------------------------------------------------------
extern "C" void kernel_launch(void* const* d_in, const int* in_sizes, int n_in,
                              void* d_out, int out_size)
{
    const float* x  = (const float*)d_in[0];
    const float* Wk = (const float*)d_in[1];
    // d_in[2] = W_query: intentionally unused (reference uses W_key for q too)
    const float* Wv = (const float*)d_in[3];
    float* out = (float*)d_out;

    cudaFuncSetAttribute(proj_kernel, cudaFuncAttributeMaxDynamicSharedMemorySize, PJ_SMEM);
    cudaFuncSetAttribute(attn_kernel, cudaFuncAttributeMaxDynamicSharedMemorySize, AT_SMEM);

    transpose_w<<<dim3(8, 32), dim3(32, 8)>>>(Wk, Wv);   // also resets counters
    proj_kernel<<<dim3(2, 128), 256, PJ_SMEM>>>(x);      // merged K/V; x shared via L2
    attn_kernel<<<dim3(8, 80), 128, AT_SMEM>>>(out);     // big items first, ~1 wave @4/SM
}